// round 12
// baseline (speedup 1.0000x reference)
#include <cuda_runtime.h>
#include <cuda_fp16.h>
#include <math.h>
#include <stdint.h>

#define N_ROWS 100000
#define IN_DIM 1024
#define DD 64
#define NQ 4
#define OUT_DIM 4

#define BR 128
#define KT 16
#define NTILES (IN_DIM / KT)    // 64
#define THREADS 256
#define STAGES 4
#define NREP 8

// ---- dynamic smem layout (bytes) ---- (identical mainloop layout to the 152us R10 kernel)
#define AS_STRIDE 24                        // floats per A row (16 data + 8 pad)
#define A_STAGE_B (BR * AS_STRIDE * 4)      // 12288
#define BS_STRIDE 24
#define B_STAGE_B (DD * BS_STRIDE * 4)      // 6144
#define A_OFF 0
#define B_OFF (STAGES * A_STAGE_B)          // 49152
#define AUX_OFF (B_OFF + STAGES * B_STAGE_B)// 73728
#define PSUM_OFF  (AUX_OFF)                 // 4 floats
#define BPS_OFF   (AUX_OFF + 64)            // 64 floats
#define WGS_OFF   (BPS_OFF + 256)           // 64 floats
#define WQS_OFF   (WGS_OFF + 256)           // 256 floats
#define CQ_OFF    (WQS_OFF + 1024)          // 4 floats
#define BG_OFF    (CQ_OFF + 16)
#define WS_OFF    (BG_OFF + 64)             // w_s: 4*128 floats = 2048B
#define SMEM_BYTES (WS_OFF + 2048 + 64)     // ~78KB -> 2 CTAs/SM

#define XS_STRIDE 65                        // xs overlays A stages post-mainloop (33280 < 49152)

// Scratch (no allocations allowed -> device globals)
__device__ float g_sum[NQ];
__device__ float g_lat8[NREP][NQ * DD];          // replicated unnormalized latent accumulators
__device__ float g_Wq[DD * NQ];                  // W_k @ latent_q^T, [d][q]
__device__ float g_c[NQ];                        // latent_q . b_k
__device__ float g_WT[(size_t)DD * IN_DIM];      // W_proj^T, [n][k]
__device__ unsigned g_ticket;

// ---- helpers ----
__device__ __forceinline__ void cp16(unsigned dst, const void* src) {
    asm volatile("cp.async.cg.shared.global [%0], [%1], 16;" :: "r"(dst), "l"(src));
}

__device__ __forceinline__ unsigned packh2(float2 v) {
    __half2 h = __floats2half2_rn(v.x, v.y);   // .x -> low half (k even), .y -> high (k odd)
    return *(unsigned*)&h;
}

__device__ __forceinline__ void mma_f16(float* c, const unsigned* a, const unsigned* b) {
    asm volatile(
        "mma.sync.aligned.m16n8k16.row.col.f32.f16.f16.f32 "
        "{%0,%1,%2,%3}, {%4,%5,%6,%7}, {%8,%9}, {%0,%1,%2,%3};"
        : "+f"(c[0]), "+f"(c[1]), "+f"(c[2]), "+f"(c[3])
        : "r"(a[0]), "r"(a[1]), "r"(a[2]), "r"(a[3]),
          "r"(b[0]), "r"(b[1]));
}

// ---------------- K0: transpose W_proj -> g_WT [n][k]; fold W_k; reset accumulators; L2 warm W_fc ----
__global__ void k0_precompute(const float* __restrict__ lq,
                              const float* __restrict__ W_k,
                              const float* __restrict__ b_k,
                              const float* __restrict__ W_proj,
                              const float* __restrict__ W_fc) {
    __shared__ float tile[16][65];
    const int t = threadIdx.x;
    const int b = blockIdx.x;          // 64 blocks; block b -> k rows [b*16, b*16+16)

    #pragma unroll
    for (int j = 0; j < 4; j++) {
        int idx = t + j * 256;
        int kk = idx >> 6, n = idx & 63;
        tile[kk][n] = W_proj[(size_t)(b * 16 + kk) * DD + n];
    }
    __syncthreads();
    #pragma unroll
    for (int j = 0; j < 4; j++) {
        int idx = t + j * 256;
        int n = idx >> 4, kk = idx & 15;
        g_WT[(size_t)n * IN_DIM + b * 16 + kk] = tile[kk][n];
    }

    // warm L2 with W_fc (64KB) from otherwise-idle blocks
    if (b >= 32 && b < 48) {
        int line = (b - 32) * 256 + t;     // 4096 lines of 16B -> covers 64KB
        if (line < 4096)
            asm volatile("prefetch.global.L2 [%0];" :: "l"(W_fc + line * 4));
    }

    if (b == 0) {
        {
            int d = t >> 2, q = t & 3;
            float s = 0.f;
            #pragma unroll
            for (int j = 0; j < DD; j++) s = fmaf(W_k[d * DD + j], lq[q * DD + j], s);
            g_Wq[d * NQ + q] = s;
        }
        if (t < NQ) {
            float s = 0.f;
            #pragma unroll
            for (int j = 0; j < DD; j++) s = fmaf(lq[t * DD + j], b_k[j], s);
            g_c[t] = s;
            g_sum[t] = 0.f;
        }
        #pragma unroll
        for (int r = 0; r < NREP; r++) g_lat8[r][t] = 0.f;
        if (t == 0) g_ticket = 0u;
    }
}

__device__ __forceinline__ void load_stage(const float* __restrict__ patch, int block_row,
                                           int tid, unsigned sbase, int s, int kt) {
    #pragma unroll
    for (int j = 0; j < 2; j++) {
        int chunk = tid + j * 256;
        int row = chunk >> 2, c = chunk & 3;
        const float* src = patch + (size_t)min(block_row + row, N_ROWS - 1) * IN_DIM + kt + c * 4;
        cp16(sbase + A_OFF + s * A_STAGE_B + row * (AS_STRIDE * 4) + c * 16, src);
    }
    {
        int n = tid >> 2, c = tid & 3;
        const float* src = g_WT + (size_t)n * IN_DIM + kt + c * 4;
        cp16(sbase + B_OFF + s * B_STAGE_B + n * (BS_STRIDE * 4) + c * 16, src);
    }
}

// ---------------- K1: fp16 MMA GEMM + gate/score/softmax-weights + latent reduction + final MLP ----
__global__ __launch_bounds__(THREADS, 2)
void k1_mma(const float* __restrict__ patch,
            const float* __restrict__ bp, const float* __restrict__ Wg,
            const float* __restrict__ bg, const unsigned char* __restrict__ mask,
            const float* __restrict__ W_fc, const float* __restrict__ b_fc,
            const float* __restrict__ W_out, const float* __restrict__ b_out,
            float* __restrict__ out_scores, float* __restrict__ logits) {
    extern __shared__ char smem[];
    const unsigned sbase = (unsigned)__cvta_generic_to_shared(smem);
    float* xs   = (float*)smem;                   // overlay of A stages (safe post-mainloop)
    float* psum = (float*)(smem + PSUM_OFF);
    float* bps  = (float*)(smem + BPS_OFF);
    float* wgs  = (float*)(smem + WGS_OFF);
    float* wqs  = (float*)(smem + WQS_OFF);
    float* cqs  = (float*)(smem + CQ_OFF);
    float* bgs  = (float*)(smem + BG_OFF);
    float* w_s  = (float*)(smem + WS_OFF);        // [NQ][BR]

    const int tid = threadIdx.x;
    const int lane = tid & 31;
    const int wid = tid >> 5;
    const int wm = wid & 3;             // row slice 0..3
    const int wn = wid >> 2;            // col slice 0..1
    const int g = lane >> 2;            // 0..7
    const int t = lane & 3;             // 0..3
    const int block_row = blockIdx.x * BR;

    if (tid < DD) { bps[tid] = bp[tid]; wgs[tid] = Wg[tid]; }
    if (tid < DD * NQ) wqs[tid] = g_Wq[tid];
    if (tid < NQ) { cqs[tid] = g_c[tid]; psum[tid] = 0.f; }
    if (tid == 0) bgs[0] = bg[0];

    float acc[2][4][4];
    #pragma unroll
    for (int mt = 0; mt < 2; mt++)
        #pragma unroll
        for (int nt = 0; nt < 4; nt++)
            #pragma unroll
            for (int i = 0; i < 4; i++) acc[mt][nt][i] = 0.f;

    // prologue: stages 0..2
    #pragma unroll
    for (int s = 0; s < STAGES - 1; s++) {
        load_stage(patch, block_row, tid, sbase, s, s * KT);
        asm volatile("cp.async.commit_group;");
    }

    for (int it = 0; it < NTILES; it++) {
        asm volatile("cp.async.wait_group 2;");
        __syncthreads();

        if (it + STAGES - 1 < NTILES)
            load_stage(patch, block_row, tid, sbase, (it + 3) & 3, (it + 3) * KT);
        asm volatile("cp.async.commit_group;");

        const float* Ab = (const float*)(smem + A_OFF + (it & 3) * A_STAGE_B);
        const float* Bb = (const float*)(smem + B_OFF + (it & 3) * B_STAGE_B);

        unsigned a[2][4];
        #pragma unroll
        for (int mt = 0; mt < 2; mt++) {
            int r0 = wm * 32 + mt * 16;
            float2 v0 = *(const float2*)(Ab + (r0 + g) * AS_STRIDE + 2 * t);
            float2 v1 = *(const float2*)(Ab + (r0 + g + 8) * AS_STRIDE + 2 * t);
            float2 v2 = *(const float2*)(Ab + (r0 + g) * AS_STRIDE + 2 * t + 8);
            float2 v3 = *(const float2*)(Ab + (r0 + g + 8) * AS_STRIDE + 2 * t + 8);
            a[mt][0] = packh2(v0); a[mt][1] = packh2(v1);
            a[mt][2] = packh2(v2); a[mt][3] = packh2(v3);
        }
        unsigned b[4][2];
        #pragma unroll
        for (int nt = 0; nt < 4; nt++) {
            int c0 = wn * 32 + nt * 8;
            float2 w0 = *(const float2*)(Bb + (c0 + g) * BS_STRIDE + 2 * t);
            float2 w1 = *(const float2*)(Bb + (c0 + g) * BS_STRIDE + 2 * t + 8);
            b[nt][0] = packh2(w0); b[nt][1] = packh2(w1);
        }
        #pragma unroll
        for (int mt = 0; mt < 2; mt++)
            #pragma unroll
            for (int nt = 0; nt < 4; nt++)
                mma_f16(acc[mt][nt], a[mt], b[nt]);
    }
    __syncthreads();   // all warps done with smem stages before xs overlay writes

    // x tile (with bias) -> smem staging only (no global x needed anymore)
    #pragma unroll
    for (int mt = 0; mt < 2; mt++) {
        #pragma unroll
        for (int nt = 0; nt < 4; nt++) {
            int col = wn * 32 + nt * 8 + t * 2;
            float b0 = bps[col], b1 = bps[col + 1];
            int lrow = wm * 32 + mt * 16 + g;
            xs[lrow * XS_STRIDE + col]     = acc[mt][nt][0] + b0;
            xs[lrow * XS_STRIDE + col + 1] = acc[mt][nt][1] + b1;
            xs[(lrow + 8) * XS_STRIDE + col]     = acc[mt][nt][2] + b0;
            xs[(lrow + 8) * XS_STRIDE + col + 1] = acc[mt][nt][3] + b1;
        }
    }
    __syncthreads();

    // gate + 4 scores + exp weights (one row per thread, tid<128)
    if (tid < BR) {
        int grow = block_row + tid;
        bool in_range = (grow < N_ROWS);
        float zg = bgs[0];
        float dq[4] = {cqs[0], cqs[1], cqs[2], cqs[3]};
        const float* xr = xs + tid * XS_STRIDE;
        #pragma unroll
        for (int d = 0; d < DD; d++) {
            float xv = xr[d];
            zg = fmaf(xv, wgs[d], zg);
            #pragma unroll
            for (int q = 0; q < NQ; q++)
                dq[q] = fmaf(xv, wqs[d * NQ + q], dq[q]);
        }
        float gate = 1.f / (1.f + expf(-zg));
        float gs = gate * 0.125f;                 // 1/sqrt(64)
        bool valid = in_range && (mask[min(grow, N_ROWS - 1)] == 0);
        float w[4];
        #pragma unroll
        for (int q = 0; q < NQ; q++) {
            float s = gs * dq[q];
            if (in_range) out_scores[(size_t)q * N_ROWS + grow] = s;
            w[q] = valid ? expf(s) : 0.f;          // softmax shift-invariant; scores O(1)
            w_s[q * BR + tid] = w[q];
        }
        #pragma unroll
        for (int q = 0; q < NQ; q++) {
            float v = w[q];
            #pragma unroll
            for (int off = 16; off > 0; off >>= 1)
                v += __shfl_xor_sync(0xffffffffu, v, off);
            if (lane == 0) atomicAdd(&psum[q], v);
        }
    }
    __syncthreads();

    // per-CTA latent partial: thread (q,d) reduces over the CTA's 128 rows
    {
        const int q = tid >> 6, d = tid & 63;
        float lacc = 0.f;
        #pragma unroll 8
        for (int r = 0; r < BR; r++)
            lacc = fmaf(w_s[q * BR + r], xs[r * XS_STRIDE + d], lacc);
        atomicAdd(&g_lat8[blockIdx.x & (NREP - 1)][tid], lacc);
    }
    if (tid < NQ) atomicAdd(&g_sum[tid], psum[tid]);

    // ---- last CTA: normalize latent + FC(relu) + out ----
    __threadfence();
    __shared__ unsigned is_last;
    if (tid == 0) is_last = (atomicAdd(&g_ticket, 1u) == (unsigned)(gridDim.x - 1));
    __syncthreads();
    if (!is_last) return;

    float* v     = xs;          // reuse (all prior xs reads complete)
    float* hpart = xs + 256;
    float* h     = xs + 512;
    {
        float s8 = 0.f;
        #pragma unroll
        for (int r = 0; r < NREP; r++) s8 += g_lat8[r][tid];
        v[tid] = s8 / g_sum[tid >> 6];
    }
    __syncthreads();
    {
        const int g4 = tid >> 6, d = tid & 63;
        float s = 0.f;
        const float* wp = W_fc + (size_t)(g4 * 64) * DD + d;
        const float* vp = v + g4 * 64;
        #pragma unroll 8
        for (int i = 0; i < 64; i++)
            s = fmaf(vp[i], wp[(size_t)i * DD], s);
        hpart[g4 * 64 + d] = s;
    }
    __syncthreads();
    if (tid < DD) {
        float s = hpart[tid] + hpart[64 + tid] + hpart[128 + tid] + hpart[192 + tid] + b_fc[tid];
        h[tid] = fmaxf(s, 0.f);
    }
    __syncthreads();
    if (tid < OUT_DIM) {
        float s = b_out[tid];
        #pragma unroll
        for (int j = 0; j < DD; j++)
            s = fmaf(h[j], W_out[j * OUT_DIM + tid], s);
        logits[tid] = s;
    }
}

extern "C" void kernel_launch(void* const* d_in, const int* in_sizes, int n_in,
                              void* d_out, int out_size) {
    const float*         patch  = (const float*)d_in[0];
    const unsigned char* mask   = (const unsigned char*)d_in[1];
    const float*         lq     = (const float*)d_in[2];
    const float*         W_proj = (const float*)d_in[3];
    const float*         b_proj = (const float*)d_in[4];
    const float*         W_k    = (const float*)d_in[5];
    const float*         b_k    = (const float*)d_in[6];
    const float*         W_gate = (const float*)d_in[7];
    const float*         b_gate = (const float*)d_in[8];
    const float*         W_fc   = (const float*)d_in[9];
    const float*         b_fc   = (const float*)d_in[10];
    const float*         W_out  = (const float*)d_in[11];
    const float*         b_out  = (const float*)d_in[12];

    float* out     = (float*)d_out;
    float* logits  = out;          // 4 floats
    float* scores  = out + 4;      // A_out: [4, 100000]

    cudaFuncSetAttribute(k1_mma, cudaFuncAttributeMaxDynamicSharedMemorySize, SMEM_BYTES);

    k0_precompute<<<64, 256>>>(lq, W_k, b_k, W_proj, W_fc);
    k1_mma<<<(N_ROWS + BR - 1) / BR, THREADS, SMEM_BYTES>>>(patch, b_proj, W_gate, b_gate, mask,
                                                            W_fc, b_fc, W_out, b_out,
                                                            scores, logits);
}

// round 13
// speedup vs baseline: 1.2723x; 1.2723x over previous
#include <cuda_runtime.h>
#include <cuda_fp16.h>
#include <math.h>
#include <stdint.h>

#define N_ROWS 100000
#define IN_DIM 1024
#define DD 64
#define NQ 4
#define OUT_DIM 4

#define BR 128
#define KT 16
#define NTILES (IN_DIM / KT)    // 64
#define THREADS 256
#define STAGES 4

// ---- dynamic smem layout (bytes) ----
#define AS_STRIDE 24                        // floats per A row (16 data + 8 pad)
#define A_STAGE_B (BR * AS_STRIDE * 4)      // 12288
#define BS_STRIDE 24                        // halfs per B row (16 data + 8 pad); (12g+t) mod 32 distinct
#define B_STAGE_B (DD * BS_STRIDE * 2)      // 3072
#define A_OFF 0
#define B_OFF (STAGES * A_STAGE_B)          // 49152
#define AUX_OFF (B_OFF + STAGES * B_STAGE_B)// 61440
#define PSUM_OFF  (AUX_OFF)                 // 4 floats
#define BPS_OFF   (AUX_OFF + 64)            // 64 floats
#define WGS_OFF   (BPS_OFF + 256)           // 64 floats
#define WQS_OFF   (WGS_OFF + 256)           // 256 floats
#define CQ_OFF    (WQS_OFF + 1024)          // 4 floats
#define BG_OFF    (CQ_OFF + 16)
#define SMEM_BYTES (AUX_OFF + 2048)         // 63488 -> 3 CTAs/SM (190KB < 228KB)

#define XS_STRIDE 65                        // xs overlays A stages post-mainloop (33280 < 49152)

#define K3_BLOCKS 1250

// Scratch (no allocations allowed -> device globals)
__device__ float g_x[(size_t)N_ROWS * DD];
__device__ float g_w[(size_t)NQ * N_ROWS];
__device__ float g_sum[NQ];
__device__ float g_latent[NQ * DD];
__device__ float g_Wq[DD * NQ];                  // W_k @ latent_q^T, [d][q]
__device__ float g_c[NQ];                        // latent_q . b_k
__device__ __half g_WTh[(size_t)DD * IN_DIM];    // W_proj^T as fp16, [n][k]
__device__ unsigned g_ticket;

// ---- helpers ----
__device__ __forceinline__ void cp16(unsigned dst, const void* src) {
    asm volatile("cp.async.cg.shared.global [%0], [%1], 16;" :: "r"(dst), "l"(src));
}

__device__ __forceinline__ unsigned packh2(float2 v) {
    __half2 h = __floats2half2_rn(v.x, v.y);   // .x -> low half (k even), .y -> high (k odd)
    return *(unsigned*)&h;
}

__device__ __forceinline__ void mma_f16(float* c, const unsigned* a, const unsigned* b) {
    asm volatile(
        "mma.sync.aligned.m16n8k16.row.col.f32.f16.f16.f32 "
        "{%0,%1,%2,%3}, {%4,%5,%6,%7}, {%8,%9}, {%0,%1,%2,%3};"
        : "+f"(c[0]), "+f"(c[1]), "+f"(c[2]), "+f"(c[3])
        : "r"(a[0]), "r"(a[1]), "r"(a[2]), "r"(a[3]),
          "r"(b[0]), "r"(b[1]));
}

// ---------------- K0: transpose W_proj -> fp16 g_WTh [n][k]; fold W_k; reset accumulators ----------------
__global__ void k0_precompute(const float* __restrict__ lq,
                              const float* __restrict__ W_k,
                              const float* __restrict__ b_k,
                              const float* __restrict__ W_proj) {
    __shared__ float tile[16][65];
    const int t = threadIdx.x;
    const int b = blockIdx.x;          // 64 blocks; block b -> k rows [b*16, b*16+16)

    #pragma unroll
    for (int j = 0; j < 4; j++) {
        int idx = t + j * 256;
        int kk = idx >> 6, n = idx & 63;
        tile[kk][n] = W_proj[(size_t)(b * 16 + kk) * DD + n];
    }
    __syncthreads();
    #pragma unroll
    for (int j = 0; j < 4; j++) {
        int idx = t + j * 256;
        int n = idx >> 4, kk = idx & 15;
        g_WTh[(size_t)n * IN_DIM + b * 16 + kk] = __float2half(tile[kk][n]);
    }

    if (b == 0) {
        {
            int d = t >> 2, q = t & 3;
            float s = 0.f;
            #pragma unroll
            for (int j = 0; j < DD; j++) s = fmaf(W_k[d * DD + j], lq[q * DD + j], s);
            g_Wq[d * NQ + q] = s;
        }
        if (t < NQ) {
            float s = 0.f;
            #pragma unroll
            for (int j = 0; j < DD; j++) s = fmaf(lq[t * DD + j], b_k[j], s);
            g_c[t] = s;
            g_sum[t] = 0.f;
        }
        g_latent[t] = 0.f;
        if (t == 0) g_ticket = 0u;
    }
}

__device__ __forceinline__ void load_stage(const float* __restrict__ patch, int block_row,
                                           int tid, unsigned sbase, int s, int kt) {
    // A: 128 rows x 16 floats -> 2 chunks of 16B per thread
    #pragma unroll
    for (int j = 0; j < 2; j++) {
        int chunk = tid + j * 256;
        int row = chunk >> 2, c = chunk & 3;
        const float* src = patch + (size_t)min(block_row + row, N_ROWS - 1) * IN_DIM + kt + c * 4;
        cp16(sbase + A_OFF + s * A_STAGE_B + row * (AS_STRIDE * 4) + c * 16, src);
    }
    // B: 64 rows x 16 halfs (32B/row) -> 128 chunks of 16B; threads 0..127
    if (tid < 128) {
        int n = tid >> 1, c = tid & 1;
        const __half* src = g_WTh + (size_t)n * IN_DIM + kt + c * 8;
        cp16(sbase + B_OFF + s * B_STAGE_B + n * (BS_STRIDE * 2) + c * 16, src);
    }
}

// ---------------- K1: fp16 m16n8k16 MMA GEMM (4-stage cp.async) + fused epilogue ----------------
__global__ __launch_bounds__(THREADS, 3)
void k1_mma(const float* __restrict__ patch,
            const float* __restrict__ bp, const float* __restrict__ Wg,
            const float* __restrict__ bg, const unsigned char* __restrict__ mask,
            float* __restrict__ out_scores) {
    extern __shared__ char smem[];
    const unsigned sbase = (unsigned)__cvta_generic_to_shared(smem);
    float* xs   = (float*)smem;                   // overlay of A stages (safe post-mainloop)
    float* psum = (float*)(smem + PSUM_OFF);
    float* bps  = (float*)(smem + BPS_OFF);
    float* wgs  = (float*)(smem + WGS_OFF);
    float* wqs  = (float*)(smem + WQS_OFF);
    float* cqs  = (float*)(smem + CQ_OFF);
    float* bgs  = (float*)(smem + BG_OFF);

    const int tid = threadIdx.x;
    const int lane = tid & 31;
    const int wid = tid >> 5;
    const int wm = wid & 3;             // row slice 0..3
    const int wn = wid >> 2;            // col slice 0..1
    const int g = lane >> 2;            // 0..7
    const int t = lane & 3;             // 0..3
    const int block_row = blockIdx.x * BR;

    if (tid < DD) { bps[tid] = bp[tid]; wgs[tid] = Wg[tid]; }
    if (tid < DD * NQ) wqs[tid] = g_Wq[tid];
    if (tid < NQ) { cqs[tid] = g_c[tid]; psum[tid] = 0.f; }
    if (tid == 0) bgs[0] = bg[0];

    float acc[2][4][4];
    #pragma unroll
    for (int mt = 0; mt < 2; mt++)
        #pragma unroll
        for (int nt = 0; nt < 4; nt++)
            #pragma unroll
            for (int i = 0; i < 4; i++) acc[mt][nt][i] = 0.f;

    // prologue: stages 0..2
    #pragma unroll
    for (int s = 0; s < STAGES - 1; s++) {
        load_stage(patch, block_row, tid, sbase, s, s * KT);
        asm volatile("cp.async.commit_group;");
    }

    for (int it = 0; it < NTILES; it++) {
        asm volatile("cp.async.wait_group 2;");
        __syncthreads();

        if (it + STAGES - 1 < NTILES)
            load_stage(patch, block_row, tid, sbase, (it + 3) & 3, (it + 3) * KT);
        asm volatile("cp.async.commit_group;");

        const float*  Ab = (const float*)(smem + A_OFF + (it & 3) * A_STAGE_B);
        const __half* Bb = (const __half*)(smem + B_OFF + (it & 3) * B_STAGE_B);

        unsigned a[2][4];
        #pragma unroll
        for (int mt = 0; mt < 2; mt++) {
            int r0 = wm * 32 + mt * 16;
            float2 v0 = *(const float2*)(Ab + (r0 + g) * AS_STRIDE + 2 * t);
            float2 v1 = *(const float2*)(Ab + (r0 + g + 8) * AS_STRIDE + 2 * t);
            float2 v2 = *(const float2*)(Ab + (r0 + g) * AS_STRIDE + 2 * t + 8);
            float2 v3 = *(const float2*)(Ab + (r0 + g + 8) * AS_STRIDE + 2 * t + 8);
            a[mt][0] = packh2(v0); a[mt][1] = packh2(v1);
            a[mt][2] = packh2(v2); a[mt][3] = packh2(v3);
        }
        unsigned b[4][2];
        #pragma unroll
        for (int nt = 0; nt < 4; nt++) {
            const __half* bpq = Bb + (wn * 32 + nt * 8 + g) * BS_STRIDE + 2 * t;
            b[nt][0] = *(const unsigned*)(bpq);
            b[nt][1] = *(const unsigned*)(bpq + 8);
        }
        #pragma unroll
        for (int mt = 0; mt < 2; mt++)
            #pragma unroll
            for (int nt = 0; nt < 4; nt++)
                mma_f16(acc[mt][nt], a[mt], b[nt]);
    }
    __syncthreads();   // all warps done with smem stages before xs overlay writes

    // store x tile: registers -> smem staging (xs overlays A stages) + global scratch
    #pragma unroll
    for (int mt = 0; mt < 2; mt++) {
        #pragma unroll
        for (int nt = 0; nt < 4; nt++) {
            int col = wn * 32 + nt * 8 + t * 2;
            float b0 = bps[col], b1 = bps[col + 1];
            int lrow = wm * 32 + mt * 16 + g;
            int row = block_row + lrow;
            float v0 = acc[mt][nt][0] + b0, v1 = acc[mt][nt][1] + b1;
            xs[lrow * XS_STRIDE + col] = v0;
            xs[lrow * XS_STRIDE + col + 1] = v1;
            if (row < N_ROWS)
                *(float2*)(g_x + (size_t)row * DD + col) = make_float2(v0, v1);
            float v2 = acc[mt][nt][2] + b0, v3 = acc[mt][nt][3] + b1;
            xs[(lrow + 8) * XS_STRIDE + col] = v2;
            xs[(lrow + 8) * XS_STRIDE + col + 1] = v3;
            if (row + 8 < N_ROWS)
                *(float2*)(g_x + (size_t)(row + 8) * DD + col) = make_float2(v2, v3);
        }
    }
    __syncthreads();

    // fused epilogue: gate + 4 scores + exp weights + partial softmax sums
    if (tid < BR) {
        int grow = block_row + tid;
        bool in_range = (grow < N_ROWS);
        float zg = bgs[0];
        float dq[4] = {cqs[0], cqs[1], cqs[2], cqs[3]};
        const float* xr = xs + tid * XS_STRIDE;
        #pragma unroll
        for (int d = 0; d < DD; d++) {
            float xv = xr[d];
            zg = fmaf(xv, wgs[d], zg);
            #pragma unroll
            for (int q = 0; q < NQ; q++)
                dq[q] = fmaf(xv, wqs[d * NQ + q], dq[q]);
        }
        float gate = 1.f / (1.f + expf(-zg));
        float gs = gate * 0.125f;                 // 1/sqrt(64)
        bool valid = in_range && (mask[min(grow, N_ROWS - 1)] == 0);
        float w[4];
        #pragma unroll
        for (int q = 0; q < NQ; q++) {
            float s = gs * dq[q];
            if (in_range) out_scores[(size_t)q * N_ROWS + grow] = s;
            w[q] = valid ? expf(s) : 0.f;          // softmax shift-invariant; scores O(1)
            if (in_range) g_w[(size_t)q * N_ROWS + grow] = w[q];
        }
        #pragma unroll
        for (int q = 0; q < NQ; q++) {
            float v = w[q];
            #pragma unroll
            for (int off = 16; off > 0; off >>= 1)
                v += __shfl_xor_sync(0xffffffffu, v, off);
            if (lane == 0) atomicAdd(&psum[q], v);
        }
    }
    __syncthreads();
    if (tid < NQ) atomicAdd(&g_sum[tid], psum[tid]);
}

// ---------------- K3: latent reduction + (last block) final FC -> logits ----------------
__global__ void k3_latent(const float* __restrict__ W_fc, const float* __restrict__ b_fc,
                          const float* __restrict__ W_out, const float* __restrict__ b_out,
                          float* __restrict__ logits) {
    const int tid = threadIdx.x;       // 256
    const int d = tid & 63;
    const int g = tid >> 6;            // 0..3 row-groups
    const int n0 = blockIdx.x * 80;

    float acc[NQ] = {0.f, 0.f, 0.f, 0.f};
    #pragma unroll
    for (int i = 0; i < 20; i++) {
        int n = n0 + g + i * 4;
        float xv = g_x[(size_t)n * DD + d];
        #pragma unroll
        for (int q = 0; q < NQ; q++)
            acc[q] = fmaf(__ldg(&g_w[(size_t)q * N_ROWS + n]), xv, acc[q]);
    }
    __shared__ float red[4][NQ][DD];
    #pragma unroll
    for (int q = 0; q < NQ; q++) red[g][q][d] = acc[q];
    __syncthreads();
    if (g == 0) {
        #pragma unroll
        for (int q = 0; q < NQ; q++) {
            float s = red[0][q][d] + red[1][q][d] + red[2][q][d] + red[3][q][d];
            atomicAdd(&g_latent[q * DD + d], s / g_sum[q]);
        }
    }

    // ---- last-block does the final MLP ----
    __threadfence();
    __shared__ unsigned is_last;
    if (tid == 0) is_last = (atomicAdd(&g_ticket, 1u) == (unsigned)(gridDim.x - 1));
    __syncthreads();
    if (!is_last) return;

    __shared__ float v[NQ * DD];
    __shared__ float hpart[4][DD];
    __shared__ float h[DD];
    v[tid] = g_latent[tid];
    __syncthreads();
    {
        float s = 0.f;
        const float* wp = W_fc + (size_t)(g * 64) * DD + d;
        const float* vp = v + g * 64;
        #pragma unroll 8
        for (int i = 0; i < 64; i++)
            s = fmaf(vp[i], wp[(size_t)i * DD], s);
        hpart[g][d] = s;
    }
    __syncthreads();
    if (tid < DD) {
        float s = hpart[0][tid] + hpart[1][tid] + hpart[2][tid] + hpart[3][tid] + b_fc[tid];
        h[tid] = fmaxf(s, 0.f);
    }
    __syncthreads();
    if (tid < OUT_DIM) {
        float s = b_out[tid];
        #pragma unroll
        for (int j = 0; j < DD; j++)
            s = fmaf(h[j], W_out[j * OUT_DIM + tid], s);
        logits[tid] = s;
    }
}

extern "C" void kernel_launch(void* const* d_in, const int* in_sizes, int n_in,
                              void* d_out, int out_size) {
    const float*         patch  = (const float*)d_in[0];
    const unsigned char* mask   = (const unsigned char*)d_in[1];
    const float*         lq     = (const float*)d_in[2];
    const float*         W_proj = (const float*)d_in[3];
    const float*         b_proj = (const float*)d_in[4];
    const float*         W_k    = (const float*)d_in[5];
    const float*         b_k    = (const float*)d_in[6];
    const float*         W_gate = (const float*)d_in[7];
    const float*         b_gate = (const float*)d_in[8];
    const float*         W_fc   = (const float*)d_in[9];
    const float*         b_fc   = (const float*)d_in[10];
    const float*         W_out  = (const float*)d_in[11];
    const float*         b_out  = (const float*)d_in[12];

    float* out     = (float*)d_out;
    float* logits  = out;          // 4 floats
    float* scores  = out + 4;      // A_out: [4, 100000]

    cudaFuncSetAttribute(k1_mma, cudaFuncAttributeMaxDynamicSharedMemorySize, SMEM_BYTES);

    k0_precompute<<<64, 256>>>(lq, W_k, b_k, W_proj);
    k1_mma<<<(N_ROWS + BR - 1) / BR, THREADS, SMEM_BYTES>>>(patch, b_proj,
                                                            W_gate, b_gate, mask, scores);
    k3_latent<<<K3_BLOCKS, 256>>>(W_fc, b_fc, W_out, b_out, logits);
}

// round 14
// speedup vs baseline: 1.3161x; 1.0344x over previous
#include <cuda_runtime.h>
#include <cuda_fp16.h>
#include <math.h>
#include <stdint.h>

#define N_ROWS 100000
#define IN_DIM 1024
#define DD 64
#define NQ 4
#define OUT_DIM 4

#define BR 128
#define KT 16
#define NTILES (IN_DIM / KT)    // 64
#define THREADS 256
#define STAGES 4

// ---- dynamic smem layout (bytes) ----
#define AS_STRIDE 24                        // floats per A row (16 data + 8 pad); LDS.64 conflict-free
#define A_STAGE_B (BR * AS_STRIDE * 4)      // 12288
#define BS_STRIDE 24                        // halfs per B row (16 data + 8 pad); (12g+t) mod 32 distinct
#define B_STAGE_B (DD * BS_STRIDE * 2)      // 3072
#define A_OFF 0
#define B_OFF (STAGES * A_STAGE_B)          // 49152
#define AUX_OFF (B_OFF + STAGES * B_STAGE_B)// 61440
#define PSUM_OFF  (AUX_OFF)                 // 4 floats
#define BPS_OFF   (AUX_OFF + 64)            // 64 floats
#define WGS_OFF   (BPS_OFF + 256)           // 64 floats
#define WQS_OFF   (WGS_OFF + 256)           // 256 floats
#define CQ_OFF    (WQS_OFF + 1024)          // 4 floats
#define BG_OFF    (CQ_OFF + 16)
#define SMEM_BYTES (AUX_OFF + 2048)         // 63488 -> 3 CTAs/SM (190KB < 228KB)

#define XS_STRIDE 65                        // xs overlays A stages post-mainloop (33280 < 49152)

#define K3_BLOCKS 1250

// Scratch (no allocations allowed -> device globals)
__device__ float g_x[(size_t)N_ROWS * DD];
__device__ float g_w4[(size_t)N_ROWS * NQ];      // [n][q] interleaved softmax weights
__device__ float g_sum[NQ];
__device__ float g_latent[NQ * DD];
__device__ float g_Wq[DD * NQ];                  // W_k @ latent_q^T, [d][q]
__device__ float g_c[NQ];                        // latent_q . b_k
__device__ __half g_WTh[(size_t)DD * IN_DIM];    // W_proj^T as fp16, [n][k]
__device__ unsigned g_ticket;

// ---- helpers ----
__device__ __forceinline__ void cp16(unsigned dst, const void* src) {
    asm volatile("cp.async.cg.shared.global [%0], [%1], 16;" :: "r"(dst), "l"(src));
}

__device__ __forceinline__ unsigned packh2(float2 v) {
    __half2 h = __floats2half2_rn(v.x, v.y);   // .x -> low half (k even), .y -> high (k odd)
    return *(unsigned*)&h;
}

__device__ __forceinline__ void mma_f16(float* c, const unsigned* a, const unsigned* b) {
    asm volatile(
        "mma.sync.aligned.m16n8k16.row.col.f32.f16.f16.f32 "
        "{%0,%1,%2,%3}, {%4,%5,%6,%7}, {%8,%9}, {%0,%1,%2,%3};"
        : "+f"(c[0]), "+f"(c[1]), "+f"(c[2]), "+f"(c[3])
        : "r"(a[0]), "r"(a[1]), "r"(a[2]), "r"(a[3]),
          "r"(b[0]), "r"(b[1]));
}

// ---------------- K0: transpose W_proj -> fp16 g_WTh [n][k]; fold W_k; reset accumulators ----------------
__global__ void k0_precompute(const float* __restrict__ lq,
                              const float* __restrict__ W_k,
                              const float* __restrict__ b_k,
                              const float* __restrict__ W_proj) {
    __shared__ float tile[16][68];     // stride 68 floats: 16B-aligned float4 slots, conflict-free STS.128
    const int t = threadIdx.x;
    const int b = blockIdx.x;          // 64 blocks; block b -> k rows [b*16, b*16+16)

    {
        int kk = t >> 4, c4 = t & 15;  // one float4 per thread: 16 rows x 16 float4
        *(float4*)&tile[kk][c4 * 4] =
            *(const float4*)(W_proj + (size_t)(b * 16 + kk) * DD + c4 * 4);
    }
    __syncthreads();
    {
        int n = t >> 2, j = t & 3;     // each thread: 4 halfs (8B) of g_WTh[n][b*16 + j*4 ..+3]
        __half2 h0 = __floats2half2_rn(tile[j * 4 + 0][n], tile[j * 4 + 1][n]);
        __half2 h1 = __floats2half2_rn(tile[j * 4 + 2][n], tile[j * 4 + 3][n]);
        uint2 v = make_uint2(*(unsigned*)&h0, *(unsigned*)&h1);
        *(uint2*)(g_WTh + (size_t)n * IN_DIM + b * 16 + j * 4) = v;
    }

    if (b == 0) {
        {
            int d = t >> 2, q = t & 3;
            float s = 0.f;
            #pragma unroll
            for (int j = 0; j < DD; j++) s = fmaf(W_k[d * DD + j], lq[q * DD + j], s);
            g_Wq[d * NQ + q] = s;
        }
        if (t < NQ) {
            float s = 0.f;
            #pragma unroll
            for (int j = 0; j < DD; j++) s = fmaf(lq[t * DD + j], b_k[j], s);
            g_c[t] = s;
            g_sum[t] = 0.f;
        }
        g_latent[t] = 0.f;
        if (t == 0) g_ticket = 0u;
    }
}

__device__ __forceinline__ void load_stage(const float* __restrict__ patch, int block_row,
                                           int tid, unsigned sbase, int s, int kt) {
    // A: 128 rows x 16 floats -> 2 chunks of 16B per thread
    #pragma unroll
    for (int j = 0; j < 2; j++) {
        int chunk = tid + j * 256;
        int row = chunk >> 2, c = chunk & 3;
        const float* src = patch + (size_t)min(block_row + row, N_ROWS - 1) * IN_DIM + kt + c * 4;
        cp16(sbase + A_OFF + s * A_STAGE_B + row * (AS_STRIDE * 4) + c * 16, src);
    }
    // B: 64 rows x 16 halfs (32B/row) -> 128 chunks of 16B; threads 0..127
    if (tid < 128) {
        int n = tid >> 1, c = tid & 1;
        const __half* src = g_WTh + (size_t)n * IN_DIM + kt + c * 8;
        cp16(sbase + B_OFF + s * B_STAGE_B + n * (BS_STRIDE * 2) + c * 16, src);
    }
}

// ---------------- K1: fp16 m16n8k16 MMA GEMM (4-stage cp.async) + fused epilogue ----------------
__global__ __launch_bounds__(THREADS, 3)
void k1_mma(const float* __restrict__ patch,
            const float* __restrict__ bp, const float* __restrict__ Wg,
            const float* __restrict__ bg, const unsigned char* __restrict__ mask,
            float* __restrict__ out_scores) {
    extern __shared__ char smem[];
    const unsigned sbase = (unsigned)__cvta_generic_to_shared(smem);
    float* xs   = (float*)smem;                   // overlay of A stages (safe post-mainloop)
    float* psum = (float*)(smem + PSUM_OFF);
    float* bps  = (float*)(smem + BPS_OFF);
    float* wgs  = (float*)(smem + WGS_OFF);
    float* wqs  = (float*)(smem + WQS_OFF);
    float* cqs  = (float*)(smem + CQ_OFF);
    float* bgs  = (float*)(smem + BG_OFF);

    const int tid = threadIdx.x;
    const int lane = tid & 31;
    const int wid = tid >> 5;
    const int wm = wid & 3;             // row slice 0..3
    const int wn = wid >> 2;            // col slice 0..1
    const int g = lane >> 2;            // 0..7
    const int t = lane & 3;             // 0..3
    const int block_row = blockIdx.x * BR;

    if (tid < DD) { bps[tid] = bp[tid]; wgs[tid] = Wg[tid]; }
    if (tid < DD * NQ) wqs[tid] = g_Wq[tid];
    if (tid < NQ) { cqs[tid] = g_c[tid]; psum[tid] = 0.f; }
    if (tid == 0) bgs[0] = bg[0];

    float acc[2][4][4];
    #pragma unroll
    for (int mt = 0; mt < 2; mt++)
        #pragma unroll
        for (int nt = 0; nt < 4; nt++)
            #pragma unroll
            for (int i = 0; i < 4; i++) acc[mt][nt][i] = 0.f;

    // prologue: stages 0..2
    #pragma unroll
    for (int s = 0; s < STAGES - 1; s++) {
        load_stage(patch, block_row, tid, sbase, s, s * KT);
        asm volatile("cp.async.commit_group;");
    }

    for (int it = 0; it < NTILES; it++) {
        asm volatile("cp.async.wait_group 2;");
        __syncthreads();

        if (it + STAGES - 1 < NTILES)
            load_stage(patch, block_row, tid, sbase, (it + 3) & 3, (it + 3) * KT);
        asm volatile("cp.async.commit_group;");

        const float*  Ab = (const float*)(smem + A_OFF + (it & 3) * A_STAGE_B);
        const __half* Bb = (const __half*)(smem + B_OFF + (it & 3) * B_STAGE_B);

        unsigned a[2][4];
        #pragma unroll
        for (int mt = 0; mt < 2; mt++) {
            int r0 = wm * 32 + mt * 16;
            float2 v0 = *(const float2*)(Ab + (r0 + g) * AS_STRIDE + 2 * t);
            float2 v1 = *(const float2*)(Ab + (r0 + g + 8) * AS_STRIDE + 2 * t);
            float2 v2 = *(const float2*)(Ab + (r0 + g) * AS_STRIDE + 2 * t + 8);
            float2 v3 = *(const float2*)(Ab + (r0 + g + 8) * AS_STRIDE + 2 * t + 8);
            a[mt][0] = packh2(v0); a[mt][1] = packh2(v1);
            a[mt][2] = packh2(v2); a[mt][3] = packh2(v3);
        }
        unsigned b[4][2];
        #pragma unroll
        for (int nt = 0; nt < 4; nt++) {
            const __half* bpq = Bb + (wn * 32 + nt * 8 + g) * BS_STRIDE + 2 * t;
            b[nt][0] = *(const unsigned*)(bpq);
            b[nt][1] = *(const unsigned*)(bpq + 8);
        }
        #pragma unroll
        for (int mt = 0; mt < 2; mt++)
            #pragma unroll
            for (int nt = 0; nt < 4; nt++)
                mma_f16(acc[mt][nt], a[mt], b[nt]);
    }
    __syncthreads();   // all warps done with smem stages before xs overlay writes

    // store x tile: registers -> smem staging (xs overlays A stages) + global scratch
    #pragma unroll
    for (int mt = 0; mt < 2; mt++) {
        #pragma unroll
        for (int nt = 0; nt < 4; nt++) {
            int col = wn * 32 + nt * 8 + t * 2;
            float b0 = bps[col], b1 = bps[col + 1];
            int lrow = wm * 32 + mt * 16 + g;
            int row = block_row + lrow;
            float v0 = acc[mt][nt][0] + b0, v1 = acc[mt][nt][1] + b1;
            xs[lrow * XS_STRIDE + col] = v0;
            xs[lrow * XS_STRIDE + col + 1] = v1;
            if (row < N_ROWS)
                *(float2*)(g_x + (size_t)row * DD + col) = make_float2(v0, v1);
            float v2 = acc[mt][nt][2] + b0, v3 = acc[mt][nt][3] + b1;
            xs[(lrow + 8) * XS_STRIDE + col] = v2;
            xs[(lrow + 8) * XS_STRIDE + col + 1] = v3;
            if (row + 8 < N_ROWS)
                *(float2*)(g_x + (size_t)(row + 8) * DD + col) = make_float2(v2, v3);
        }
    }
    __syncthreads();

    // fused epilogue: gate + 4 scores + exp weights + partial softmax sums
    if (tid < BR) {
        int grow = block_row + tid;
        bool in_range = (grow < N_ROWS);
        float zg = bgs[0];
        float dq[4] = {cqs[0], cqs[1], cqs[2], cqs[3]};
        const float* xr = xs + tid * XS_STRIDE;
        #pragma unroll
        for (int d = 0; d < DD; d++) {
            float xv = xr[d];
            zg = fmaf(xv, wgs[d], zg);
            #pragma unroll
            for (int q = 0; q < NQ; q++)
                dq[q] = fmaf(xv, wqs[d * NQ + q], dq[q]);
        }
        float gate = 1.f / (1.f + expf(-zg));
        float gs = gate * 0.125f;                 // 1/sqrt(64)
        bool valid = in_range && (mask[min(grow, N_ROWS - 1)] == 0);
        float w[4];
        #pragma unroll
        for (int q = 0; q < NQ; q++) {
            float s = gs * dq[q];
            if (in_range) out_scores[(size_t)q * N_ROWS + grow] = s;
            w[q] = valid ? expf(s) : 0.f;          // softmax shift-invariant; scores O(1)
        }
        if (in_range)
            *(float4*)(g_w4 + (size_t)grow * NQ) = make_float4(w[0], w[1], w[2], w[3]);
        #pragma unroll
        for (int q = 0; q < NQ; q++) {
            float v = w[q];
            #pragma unroll
            for (int off = 16; off > 0; off >>= 1)
                v += __shfl_xor_sync(0xffffffffu, v, off);
            if (lane == 0) atomicAdd(&psum[q], v);
        }
    }
    __syncthreads();
    if (tid < NQ) atomicAdd(&g_sum[tid], psum[tid]);
}

// ---------------- K3: latent reduction + (last block) final FC -> logits ----------------
__global__ void k3_latent(const float* __restrict__ W_fc, const float* __restrict__ b_fc,
                          const float* __restrict__ W_out, const float* __restrict__ b_out,
                          float* __restrict__ logits) {
    const int tid = threadIdx.x;       // 256
    const int d = tid & 63;
    const int g = tid >> 6;            // 0..3 row-groups
    const int n0 = blockIdx.x * 80;

    float acc[NQ] = {0.f, 0.f, 0.f, 0.f};
    #pragma unroll
    for (int i = 0; i < 20; i++) {
        int n = n0 + g + i * 4;
        float xv = g_x[(size_t)n * DD + d];
        float4 wv = *(const float4*)(g_w4 + (size_t)n * NQ);   // broadcast across 64 lanes
        acc[0] = fmaf(wv.x, xv, acc[0]);
        acc[1] = fmaf(wv.y, xv, acc[1]);
        acc[2] = fmaf(wv.z, xv, acc[2]);
        acc[3] = fmaf(wv.w, xv, acc[3]);
    }
    __shared__ float red[4][NQ][DD];
    #pragma unroll
    for (int q = 0; q < NQ; q++) red[g][q][d] = acc[q];
    __syncthreads();
    if (g == 0) {
        #pragma unroll
        for (int q = 0; q < NQ; q++) {
            float s = red[0][q][d] + red[1][q][d] + red[2][q][d] + red[3][q][d];
            atomicAdd(&g_latent[q * DD + d], s / g_sum[q]);
        }
    }

    // ---- last-block does the final MLP ----
    __threadfence();
    __shared__ unsigned is_last;
    if (tid == 0) is_last = (atomicAdd(&g_ticket, 1u) == (unsigned)(gridDim.x - 1));
    __syncthreads();
    if (!is_last) return;

    __shared__ float v[NQ * DD];
    __shared__ float hpart[4][DD];
    __shared__ float h[DD];
    v[tid] = g_latent[tid];
    __syncthreads();
    {
        float s = 0.f;
        const float* wp = W_fc + (size_t)(g * 64) * DD + d;
        const float* vp = v + g * 64;
        #pragma unroll 8
        for (int i = 0; i < 64; i++)
            s = fmaf(vp[i], wp[(size_t)i * DD], s);
        hpart[g][d] = s;
    }
    __syncthreads();
    if (tid < DD) {
        float s = hpart[0][tid] + hpart[1][tid] + hpart[2][tid] + hpart[3][tid] + b_fc[tid];
        h[tid] = fmaxf(s, 0.f);
    }
    __syncthreads();
    if (tid < OUT_DIM) {
        float s = b_out[tid];
        #pragma unroll
        for (int j = 0; j < DD; j++)
            s = fmaf(h[j], W_out[j * OUT_DIM + tid], s);
        logits[tid] = s;
    }
}

extern "C" void kernel_launch(void* const* d_in, const int* in_sizes, int n_in,
                              void* d_out, int out_size) {
    const float*         patch  = (const float*)d_in[0];
    const unsigned char* mask   = (const unsigned char*)d_in[1];
    const float*         lq     = (const float*)d_in[2];
    const float*         W_proj = (const float*)d_in[3];
    const float*         b_proj = (const float*)d_in[4];
    const float*         W_k    = (const float*)d_in[5];
    const float*         b_k    = (const float*)d_in[6];
    const float*         W_gate = (const float*)d_in[7];
    const float*         b_gate = (const float*)d_in[8];
    const float*         W_fc   = (const float*)d_in[9];
    const float*         b_fc   = (const float*)d_in[10];
    const float*         W_out  = (const float*)d_in[11];
    const float*         b_out  = (const float*)d_in[12];

    float* out     = (float*)d_out;
    float* logits  = out;          // 4 floats
    float* scores  = out + 4;      // A_out: [4, 100000]

    cudaFuncSetAttribute(k1_mma, cudaFuncAttributeMaxDynamicSharedMemorySize, SMEM_BYTES);

    k0_precompute<<<64, 256>>>(lq, W_k, b_k, W_proj);
    k1_mma<<<(N_ROWS + BR - 1) / BR, THREADS, SMEM_BYTES>>>(patch, b_proj,
                                                            W_gate, b_gate, mask, scores);
    k3_latent<<<K3_BLOCKS, 256>>>(W_fc, b_fc, W_out, b_out, logits);
}